// round 1
// baseline (speedup 1.0000x reference)
#include <cuda_runtime.h>
#include <float.h>

#define NPROP 1024
#define NC    81
#define NCLS  80
#define FD    1024
#define KTOP  100
#define CAP   (NCLS * NPROP)

#define SCORE_TH 0.05f
#define NMS_TH   0.5f
#define BBOX_CLIP 4.135166556742356f
#define IMG_W_M1 1215.0f
#define IMG_H_M1 799.0f

// ---------------- device scratch (static globals; no allocation) ------------
__device__ float g_scoresT[NCLS * NPROP];       // [c][n] score of class c+1
__device__ float g_decT[NCLS * NPROP * 4];      // [c][n][4] decoded+clipped boxes
__device__ int   g_count;
__device__ float g_cscore[CAP];
__device__ float g_cbox[CAP * 4];
__device__ int   g_corig[CAP];
__device__ int   g_cflat[CAP];
__device__ int   g_clabel[CAP];
__device__ int   g_sel[KTOP];
__device__ float g_selscore[KTOP];

// ---------------- Kernel A: softmax + decode + clip -------------------------
__global__ void kA(const float* __restrict__ logits,
                   const float* __restrict__ reg,
                   const float* __restrict__ props) {
    int n = blockIdx.x;
    int t = threadIdx.x;
    __shared__ float red[128];

    float v = (t < NC) ? logits[n * NC + t] : -FLT_MAX;
    red[t] = v;
    __syncthreads();
    for (int s = 64; s > 0; s >>= 1) {
        if (t < s) red[t] = fmaxf(red[t], red[t + s]);
        __syncthreads();
    }
    float m = red[0];
    __syncthreads();
    float e = (t < NC) ? expf(v - m) : 0.0f;
    red[t] = e;
    __syncthreads();
    for (int s = 64; s > 0; s >>= 1) {
        if (t < s) red[t] += red[t + s];
        __syncthreads();
    }
    float sum = red[0];

    if (t >= 1 && t < NC) {
        int c = t - 1;
        float prob = e / sum;
        g_scoresT[c * NPROP + n] = prob;

        float x1 = props[n * 4 + 0];
        float y1 = props[n * 4 + 1];
        float x2 = props[n * 4 + 2];
        float y2 = props[n * 4 + 3];
        float w  = x2 - x1 + 1.0f;
        float h  = y2 - y1 + 1.0f;
        float cx = x1 + 0.5f * w;
        float cy = y1 + 0.5f * h;

        const float* r = reg + n * NC * 4 + t * 4;
        float dx = r[0] / 10.0f;
        float dy = r[1] / 10.0f;
        float dw = fminf(r[2] / 5.0f, BBOX_CLIP);
        float dh = fminf(r[3] / 5.0f, BBOX_CLIP);

        float pcx = dx * w + cx;
        float pcy = dy * h + cy;
        float pw  = expf(dw) * w;
        float ph  = expf(dh) * h;

        float bx1 = pcx - 0.5f * pw;
        float by1 = pcy - 0.5f * ph;
        float bx2 = pcx + 0.5f * pw - 1.0f;
        float by2 = pcy + 0.5f * ph - 1.0f;

        bx1 = fminf(fmaxf(bx1, 0.0f), IMG_W_M1);
        by1 = fminf(fmaxf(by1, 0.0f), IMG_H_M1);
        bx2 = fminf(fmaxf(bx2, 0.0f), IMG_W_M1);
        by2 = fminf(fmaxf(by2, 0.0f), IMG_H_M1);

        float* d = g_decT + (size_t)(c * NPROP + n) * 4;
        d[0] = bx1; d[1] = by1; d[2] = bx2; d[3] = by2;
    }
    if (n == 0 && t == 0) g_count = 0;
}

// ---------------- Kernel B: per-class sort + greedy NMS + compact ------------
__global__ void kB() {
    int c = blockIdx.x;
    int t = threadIdx.x;

    __shared__ float skey[NPROP];
    __shared__ int   sidx[NPROP];
    __shared__ float sx1[NPROP], sy1[NPROP], sx2[NPROP], sy2[NPROP], sarea[NPROP];
    __shared__ unsigned char skeep[NPROP];
    __shared__ int sh_nv;

    float s = g_scoresT[c * NPROP + t];
    skey[t] = (s > SCORE_TH) ? s : -1.0f;   // invalid -> -1 (all valid > 0.05)
    sidx[t] = t;
    __syncthreads();

    // bitonic sort: score descending, index ascending on ties (stable argsort(-s))
    for (int k = 2; k <= NPROP; k <<= 1) {
        for (int j = k >> 1; j > 0; j >>= 1) {
            int ixj = t ^ j;
            if (ixj > t) {
                float ka = skey[t], kb = skey[ixj];
                int   ia = sidx[t], ib = sidx[ixj];
                // true if ixj's element should precede t's in target order
                bool oo = (kb > ka) || (kb == ka && ib < ia);
                if (((t & k) == 0) == oo) {
                    skey[t] = kb; skey[ixj] = ka;
                    sidx[t] = ib; sidx[ixj] = ia;
                }
            }
            __syncthreads();
        }
    }

    // load sorted boxes
    int orig = sidx[t];
    const float* d = g_decT + (size_t)(c * NPROP + orig) * 4;
    float a0 = d[0], a1 = d[1], a2 = d[2], a3 = d[3];
    sx1[t] = a0; sy1[t] = a1; sx2[t] = a2; sy2[t] = a3;
    sarea[t] = (a2 - a0 + 1.0f) * (a3 - a1 + 1.0f);
    skeep[t] = (skey[t] > 0.0f) ? 1 : 0;
    if (t == 0) sh_nv = NPROP;
    __syncthreads();
    if (skey[t] < 0.0f && (t == 0 || skey[t - 1] >= 0.0f)) sh_nv = t;
    __syncthreads();
    int nv = sh_nv;

    // greedy NMS
    for (int i = 0; i < nv; i++) {
        __syncthreads();
        if (!skeep[i]) continue;
        if (t > i && skeep[t]) {
            float xx1 = fmaxf(sx1[t], sx1[i]);
            float yy1 = fmaxf(sy1[t], sy1[i]);
            float xx2 = fminf(sx2[t], sx2[i]);
            float yy2 = fminf(sy2[t], sy2[i]);
            float iw = fmaxf(xx2 - xx1 + 1.0f, 0.0f);
            float ih = fmaxf(yy2 - yy1 + 1.0f, 0.0f);
            float inter = iw * ih;
            float iou = inter / (sarea[t] + sarea[i] - inter);
            if (iou > NMS_TH) skeep[t] = 0;
        }
    }
    __syncthreads();

    // compact survivors
    if (t < nv && skeep[t]) {
        int p = atomicAdd(&g_count, 1);
        g_cscore[p] = skey[t];
        float* gb = g_cbox + (size_t)p * 4;
        gb[0] = sx1[t]; gb[1] = sy1[t]; gb[2] = sx2[t]; gb[3] = sy2[t];
        g_corig[p]  = sidx[t];
        g_cflat[p]  = c * NPROP + t;
        g_clabel[p] = c + 1;
    }
}

// ---------------- Kernel C: top-K by (score desc, flatidx asc) --------------
__global__ void kC() {
    int t = threadIdx.x;
    int M = g_count;
    if (M > CAP) M = CAP;
    __shared__ float ws[32];
    __shared__ int   wf[32];
    __shared__ int   wi[32];

    for (int k = 0; k < KTOP; k++) {
        float bs = -FLT_MAX;
        int   bf = 0x7fffffff;
        int   bi = -1;
        for (int i = t; i < M; i += 1024) {
            float s = g_cscore[i];
            int   f = g_cflat[i];
            if (s > bs || (s == bs && f < bf)) { bs = s; bf = f; bi = i; }
        }
        for (int off = 16; off; off >>= 1) {
            float s2 = __shfl_down_sync(0xffffffffu, bs, off);
            int   f2 = __shfl_down_sync(0xffffffffu, bf, off);
            int   i2 = __shfl_down_sync(0xffffffffu, bi, off);
            if (s2 > bs || (s2 == bs && f2 < bf)) { bs = s2; bf = f2; bi = i2; }
        }
        int w = t >> 5, l = t & 31;
        if (l == 0) { ws[w] = bs; wf[w] = bf; wi[w] = bi; }
        __syncthreads();
        if (w == 0) {
            bs = ws[l]; bf = wf[l]; bi = wi[l];
            for (int off = 16; off; off >>= 1) {
                float s2 = __shfl_down_sync(0xffffffffu, bs, off);
                int   f2 = __shfl_down_sync(0xffffffffu, bf, off);
                int   i2 = __shfl_down_sync(0xffffffffu, bi, off);
                if (s2 > bs || (s2 == bs && f2 < bf)) { bs = s2; bf = f2; bi = i2; }
            }
            if (l == 0) {
                if (bs > 0.0f && bi >= 0) {
                    g_sel[k] = bi;
                    g_selscore[k] = bs;
                    g_cscore[bi] = -FLT_MAX;   // exclude from later iterations
                } else {
                    g_sel[k] = -1;
                    g_selscore[k] = 0.0f;
                }
            }
        }
        __syncthreads();
    }
}

// ---------------- Kernel D: write outputs + feature gather ------------------
__global__ void kD(const float* __restrict__ feats, float* __restrict__ out) {
    int k = blockIdx.x;
    int t = threadIdx.x;
    int sel = g_sel[k];
    const int OB = 0;
    const int OS = KTOP * 4;
    const int OF = KTOP * 4 + KTOP;
    const int OL = KTOP * 4 + KTOP + KTOP * FD;

    if (sel >= 0) {
        if (t == 0) {
            const float* gb = g_cbox + (size_t)sel * 4;
            out[OB + k * 4 + 0] = gb[0];
            out[OB + k * 4 + 1] = gb[1];
            out[OB + k * 4 + 2] = gb[2];
            out[OB + k * 4 + 3] = gb[3];
            out[OS + k] = g_selscore[k];
            out[OL + k] = (float)g_clabel[sel];
        }
        int orig = g_corig[sel];
        const float4* src = (const float4*)(feats + (size_t)orig * FD);
        float4* dst = (float4*)(out + OF + (size_t)k * FD);
        dst[t] = src[t];   // 256 threads x float4 = 1024 floats
    } else {
        if (t == 0) {
            out[OB + k * 4 + 0] = 0.0f;
            out[OB + k * 4 + 1] = 0.0f;
            out[OB + k * 4 + 2] = 0.0f;
            out[OB + k * 4 + 3] = 0.0f;
            out[OS + k] = 0.0f;
            out[OL + k] = 0.0f;
        }
        float4 z = make_float4(0.0f, 0.0f, 0.0f, 0.0f);
        float4* dst = (float4*)(out + OF + (size_t)k * FD);
        dst[t] = z;
    }
}

// ---------------- launch -----------------------------------------------------
extern "C" void kernel_launch(void* const* d_in, const int* in_sizes, int n_in,
                              void* d_out, int out_size) {
    const float* logits = (const float*)d_in[0];   // [N,81]
    const float* reg    = (const float*)d_in[1];   // [N,324]
    const float* props  = (const float*)d_in[2];   // [N,4]
    const float* feats  = (const float*)d_in[3];   // [N,1024]
    float* out = (float*)d_out;                    // 103000 floats

    kA<<<NPROP, 128>>>(logits, reg, props);
    kB<<<NCLS, NPROP>>>();
    kC<<<1, 1024>>>();
    kD<<<KTOP, 256>>>(feats, out);
}

// round 2
// speedup vs baseline: 3.4329x; 3.4329x over previous
#include <cuda_runtime.h>
#include <float.h>

#define NPROP 1024
#define NC    81
#define NCLS  80
#define FD    1024
#define KTOP  100
#define CAP   (NCLS * KTOP)      // per-class survivor cap 100 -> max 8000 candidates

#define SCORE_TH 0.05f
#define NMS_TH   0.5f
#define BBOX_CLIP 4.135166556742356f
#define IMG_W_M1 1215.0f
#define IMG_H_M1 799.0f

// ---------------- device scratch ------------
__device__ float g_scoresT[NCLS * NPROP];       // [c][n] score of class c+1
__device__ float g_decT[NCLS * NPROP * 4];      // [c][n][4] decoded boxes (only valid entries written)
__device__ int   g_count;
__device__ float g_cscore[CAP];
__device__ float g_cbox[CAP * 4];
__device__ int   g_corig[CAP];
__device__ int   g_cflat[CAP];
__device__ int   g_clabel[CAP];
__device__ int   g_sel[KTOP];
__device__ float g_selscore[KTOP];

// ---------------- Kernel A: softmax + (sparse) decode + clip ----------------
__global__ void kA(const float* __restrict__ logits,
                   const float* __restrict__ reg,
                   const float* __restrict__ props) {
    int n = blockIdx.x;
    int t = threadIdx.x;
    __shared__ float red[128];

    float v = (t < NC) ? logits[n * NC + t] : -FLT_MAX;
    red[t] = v;
    __syncthreads();
    for (int s = 64; s > 0; s >>= 1) {
        if (t < s) red[t] = fmaxf(red[t], red[t + s]);
        __syncthreads();
    }
    float m = red[0];
    __syncthreads();
    float e = (t < NC) ? expf(v - m) : 0.0f;
    red[t] = e;
    __syncthreads();
    for (int s = 64; s > 0; s >>= 1) {
        if (t < s) red[t] += red[t + s];
        __syncthreads();
    }
    float sum = red[0];

    if (t >= 1 && t < NC) {
        int c = t - 1;
        float prob = e / sum;
        g_scoresT[c * NPROP + n] = prob;

        if (prob > SCORE_TH) {            // only valid entries ever get read
            float x1 = props[n * 4 + 0];
            float y1 = props[n * 4 + 1];
            float x2 = props[n * 4 + 2];
            float y2 = props[n * 4 + 3];
            float w  = x2 - x1 + 1.0f;
            float h  = y2 - y1 + 1.0f;
            float cx = x1 + 0.5f * w;
            float cy = y1 + 0.5f * h;

            const float* r = reg + n * NC * 4 + t * 4;
            float dx = r[0] / 10.0f;
            float dy = r[1] / 10.0f;
            float dw = fminf(r[2] / 5.0f, BBOX_CLIP);
            float dh = fminf(r[3] / 5.0f, BBOX_CLIP);

            float pcx = dx * w + cx;
            float pcy = dy * h + cy;
            float pw  = expf(dw) * w;
            float ph  = expf(dh) * h;

            float bx1 = pcx - 0.5f * pw;
            float by1 = pcy - 0.5f * ph;
            float bx2 = pcx + 0.5f * pw - 1.0f;
            float by2 = pcy + 0.5f * ph - 1.0f;

            bx1 = fminf(fmaxf(bx1, 0.0f), IMG_W_M1);
            by1 = fminf(fmaxf(by1, 0.0f), IMG_H_M1);
            bx2 = fminf(fmaxf(bx2, 0.0f), IMG_W_M1);
            by2 = fminf(fmaxf(by2, 0.0f), IMG_H_M1);

            float* d = g_decT + (size_t)(c * NPROP + n) * 4;
            d[0] = bx1; d[1] = by1; d[2] = bx2; d[3] = by2;
        }
    }
    if (n == 0) {
        if (t == 0) g_count = 0;
        if (t < KTOP) { g_sel[t] = -1; g_selscore[t] = 0.0f; }
    }
}

// ---------------- Kernel B: compact + rank-sort + mask NMS + compact --------
// dynamic shared layout (words):
//  u_sc[1024] | u_idx[1024] | skey[1024] | sorig[1024] |
//  sx1[1024] sy1[1024] sx2[1024] sy2[1024] sarea[1024] |
//  mask[1024*32] | remove[32] | cnt[1]
#define KB_THREADS 256
#define KB_SMEM_WORDS (9 * 1024 + 1024 * 32 + 32 + 1)
#define KB_SMEM_BYTES (KB_SMEM_WORDS * 4)

__global__ void kB() {
    extern __shared__ unsigned int sm[];
    float*    u_sc   = (float*)sm;
    int*      u_idx  = (int*)(sm + 1024);
    float*    skey   = (float*)(sm + 2048);
    int*      sorig  = (int*)(sm + 3072);
    float*    sx1    = (float*)(sm + 4096);
    float*    sy1    = (float*)(sm + 5120);
    float*    sx2    = (float*)(sm + 6144);
    float*    sy2    = (float*)(sm + 7168);
    float*    sarea  = (float*)(sm + 8192);
    unsigned* mask   = sm + 9216;
    unsigned* s_rem  = sm + 9216 + 32768;
    int*      s_cnt  = (int*)(s_rem + 32);

    int c = blockIdx.x;
    int t = threadIdx.x;

    if (t == 0) *s_cnt = 0;
    __syncthreads();

    // --- phase 1: compact valid entries (unordered) ---
    for (int e = t; e < NPROP; e += KB_THREADS) {
        float s = g_scoresT[c * NPROP + e];
        if (s > SCORE_TH) {
            int p = atomicAdd(s_cnt, 1);
            u_sc[p]  = s;
            u_idx[p] = e;
        }
    }
    __syncthreads();
    int nv = *s_cnt;
    if (nv == 0) return;
    int nwords = (nv + 31) >> 5;

    // --- phase 2: rank-sort (score desc, orig idx asc) ---
    for (int ii = t; ii < nv; ii += KB_THREADS) {
        float ms = u_sc[ii];
        int   mi = u_idx[ii];
        int   r  = 0;
        for (int j = 0; j < nv; j++) {
            float sj = u_sc[j];
            int   ij = u_idx[j];
            r += (sj > ms) || (sj == ms && ij < mi);
        }
        skey[r]  = ms;
        sorig[r] = mi;
        const float* d = g_decT + (size_t)(c * NPROP + mi) * 4;
        float a0 = d[0], a1 = d[1], a2 = d[2], a3 = d[3];
        sx1[r] = a0; sy1[r] = a1; sx2[r] = a2; sy2[r] = a3;
        sarea[r] = (a2 - a0 + 1.0f) * (a3 - a1 + 1.0f);
    }
    __syncthreads();

    // --- phase 3: IoU suppression bitmask (bit j of mask[i][w]: i suppresses j) ---
    int cells = nv * nwords;
    for (int cell = t; cell < cells; cell += KB_THREADS) {
        int i = cell / nwords;
        int w = cell - i * nwords;
        float x1 = sx1[i], y1 = sy1[i], x2 = sx2[i], y2 = sy2[i], ai = sarea[i];
        unsigned mword = 0;
        int jbase = w << 5;
        #pragma unroll 4
        for (int b = 0; b < 32; b++) {
            int j = jbase + b;
            if (j > i && j < nv) {
                float xx1 = fmaxf(x1, sx1[j]);
                float yy1 = fmaxf(y1, sy1[j]);
                float xx2 = fminf(x2, sx2[j]);
                float yy2 = fminf(y2, sy2[j]);
                float iw = fmaxf(xx2 - xx1 + 1.0f, 0.0f);
                float ih = fmaxf(yy2 - yy1 + 1.0f, 0.0f);
                float inter = iw * ih;
                float iou = inter / (ai + sarea[j] - inter);
                if (iou > NMS_TH) mword |= (1u << b);
            }
        }
        mask[(i << 5) + w] = mword;
    }
    if (t < 32 && t >= nwords) s_rem[t] = 0;   // untouched words zero
    __syncthreads();

    // --- phase 4: greedy pass over kept boxes only (warp 0; lane w owns word w) ---
    if (t < 32) {
        unsigned rem = 0;
        for (int wi = 0; wi < nwords; wi++) {
            unsigned remw = __shfl_sync(0xffffffffu, rem, wi);
            int rembits = nv - (wi << 5);
            unsigned validm = (rembits >= 32) ? 0xffffffffu : ((1u << rembits) - 1u);
            unsigned alive = (~remw) & validm;
            while (alive) {
                int b = __ffs(alive) - 1;
                int i = (wi << 5) + b;
                unsigned row = (t < nwords) ? mask[(i << 5) + t] : 0u;
                rem |= row;
                alive &= ~(1u << b);
                alive &= ~__shfl_sync(0xffffffffu, row, wi);
            }
        }
        if (t < nwords) s_rem[t] = rem;
    }
    __syncthreads();

    // --- phase 5: compact survivors (first KTOP per class only) ---
    for (int i = t; i < nv; i += KB_THREADS) {
        unsigned rw = s_rem[i >> 5];
        if (!((rw >> (i & 31)) & 1)) {
            int kr = 0;
            for (int w = 0; w < (i >> 5); w++) kr += __popc(~s_rem[w]);
            kr += __popc((~rw) & ((1u << (i & 31)) - 1u));
            if (kr < KTOP) {
                int p = atomicAdd(&g_count, 1);
                g_cscore[p] = skey[i];
                float* gb = g_cbox + (size_t)p * 4;
                gb[0] = sx1[i]; gb[1] = sy1[i]; gb[2] = sx2[i]; gb[3] = sy2[i];
                g_corig[p]  = sorig[i];
                g_cflat[p]  = c * NPROP + i;
                g_clabel[p] = c + 1;
            }
        }
    }
}

// ---------------- Kernel C: parallel rank top-K -----------------------------
#define TK_THREADS 256
#define TK_BLOCKS  ((CAP + TK_THREADS - 1) / TK_THREADS)

__device__ __forceinline__ unsigned long long tk_key(float s, int flat) {
    return (((unsigned long long)__float_as_uint(s)) << 32) |
           (unsigned long long)(0xFFFFFFFFu - (unsigned)flat);
}

__global__ void kTop() {
    int M = g_count;
    if (M > CAP) M = CAP;
    __shared__ unsigned long long tile[TK_THREADS];
    int gsz = gridDim.x * TK_THREADS;

    for (int base = 0; base < M; base += gsz) {
        int i = base + blockIdx.x * TK_THREADS + threadIdx.x;
        bool act = (i < M);
        unsigned long long mykey = act ? tk_key(g_cscore[i], g_cflat[i]) : 0ull;
        int rank = 0;
        for (int tb = 0; tb < M; tb += TK_THREADS) {
            int j = tb + threadIdx.x;
            tile[threadIdx.x] = (j < M) ? tk_key(g_cscore[j], g_cflat[j]) : 0ull;
            __syncthreads();
            int lim = min(TK_THREADS, M - tb);
            if (act && rank < KTOP) {
                for (int jj = 0; jj < lim; jj++) rank += (tile[jj] > mykey);
            }
            __syncthreads();
        }
        if (act && rank < KTOP) {
            g_sel[rank] = i;
            g_selscore[rank] = g_cscore[i];
        }
    }
}

// ---------------- Kernel D: write outputs + feature gather ------------------
__global__ void kD(const float* __restrict__ feats, float* __restrict__ out) {
    int k = blockIdx.x;
    int t = threadIdx.x;
    int sel = g_sel[k];
    const int OB = 0;
    const int OS = KTOP * 4;
    const int OF = KTOP * 4 + KTOP;
    const int OL = KTOP * 4 + KTOP + KTOP * FD;

    if (sel >= 0) {
        if (t == 0) {
            const float* gb = g_cbox + (size_t)sel * 4;
            out[OB + k * 4 + 0] = gb[0];
            out[OB + k * 4 + 1] = gb[1];
            out[OB + k * 4 + 2] = gb[2];
            out[OB + k * 4 + 3] = gb[3];
            out[OS + k] = g_selscore[k];
            out[OL + k] = (float)g_clabel[sel];
        }
        int orig = g_corig[sel];
        const float4* src = (const float4*)(feats + (size_t)orig * FD);
        float4* dst = (float4*)(out + OF + (size_t)k * FD);
        dst[t] = src[t];
    } else {
        if (t == 0) {
            out[OB + k * 4 + 0] = 0.0f;
            out[OB + k * 4 + 1] = 0.0f;
            out[OB + k * 4 + 2] = 0.0f;
            out[OB + k * 4 + 3] = 0.0f;
            out[OS + k] = 0.0f;
            out[OL + k] = 0.0f;
        }
        float4 z = make_float4(0.0f, 0.0f, 0.0f, 0.0f);
        float4* dst = (float4*)(out + OF + (size_t)k * FD);
        dst[t] = z;
    }
}

// ---------------- launch -----------------------------------------------------
extern "C" void kernel_launch(void* const* d_in, const int* in_sizes, int n_in,
                              void* d_out, int out_size) {
    const float* logits = (const float*)d_in[0];   // [N,81]
    const float* reg    = (const float*)d_in[1];   // [N,324]
    const float* props  = (const float*)d_in[2];   // [N,4]
    const float* feats  = (const float*)d_in[3];   // [N,1024]
    float* out = (float*)d_out;

    static bool attr_done = false;
    if (!attr_done) {
        cudaFuncSetAttribute(kB, cudaFuncAttributeMaxDynamicSharedMemorySize,
                             KB_SMEM_BYTES);
        attr_done = true;
    }

    kA<<<NPROP, 128>>>(logits, reg, props);
    kB<<<NCLS, KB_THREADS, KB_SMEM_BYTES>>>();
    kTop<<<TK_BLOCKS, TK_THREADS>>>();
    kD<<<KTOP, 256>>>(feats, out);
}

// round 4
// speedup vs baseline: 4.7512x; 1.3840x over previous
#include <cuda_runtime.h>
#include <float.h>

#define NPROP 1024
#define NC    81
#define NCLS  80
#define FD    1024
#define KTOP  100
#define CAP   (NCLS * KTOP)

#define SCORE_TH 0.05f
#define NMS_TH   0.5f
#define BBOX_CLIP 4.135166556742356f
#define IMG_W_M1 1215.0f
#define IMG_H_M1 799.0f

// ---------------- device scratch ------------
__device__ float g_scoresT[NCLS * NPROP];
__device__ float g_decT[NCLS * NPROP * 4];
__device__ int   g_count;
__device__ float g_cscore[CAP];
__device__ float g_cbox[CAP * 4];
__device__ int   g_corig[CAP];
__device__ int   g_cflat[CAP];
__device__ int   g_clabel[CAP];
__device__ int   g_sel[KTOP];
__device__ float g_selscore[KTOP];

// ---------------- Kernel A: softmax (warp reduce) + sparse decode -----------
__global__ void kA(const float* __restrict__ logits,
                   const float* __restrict__ reg,
                   const float* __restrict__ props) {
    int n = blockIdx.x;
    int t = threadIdx.x;
    int w = t >> 5, l = t & 31;
    __shared__ float pmax[4], psum[4];

    float v = (t < NC) ? logits[n * NC + t] : -FLT_MAX;

    // block max via warp shuffles
    float m = v;
    #pragma unroll
    for (int off = 16; off; off >>= 1)
        m = fmaxf(m, __shfl_xor_sync(0xffffffffu, m, off));
    if (l == 0) pmax[w] = m;
    __syncthreads();
    m = fmaxf(fmaxf(pmax[0], pmax[1]), fmaxf(pmax[2], pmax[3]));

    float e = (t < NC) ? expf(v - m) : 0.0f;
    float s = e;
    #pragma unroll
    for (int off = 16; off; off >>= 1)
        s += __shfl_xor_sync(0xffffffffu, s, off);
    if (l == 0) psum[w] = s;
    __syncthreads();
    float sum = psum[0] + psum[1] + psum[2] + psum[3];

    if (t >= 1 && t < NC) {
        int c = t - 1;
        float prob = e / sum;
        g_scoresT[c * NPROP + n] = prob;

        if (prob > SCORE_TH) {
            float x1 = props[n * 4 + 0];
            float y1 = props[n * 4 + 1];
            float x2 = props[n * 4 + 2];
            float y2 = props[n * 4 + 3];
            float bw = x2 - x1 + 1.0f;
            float bh = y2 - y1 + 1.0f;
            float cx = x1 + 0.5f * bw;
            float cy = y1 + 0.5f * bh;

            const float* r = reg + n * NC * 4 + t * 4;
            float dx = r[0] / 10.0f;
            float dy = r[1] / 10.0f;
            float dw = fminf(r[2] / 5.0f, BBOX_CLIP);
            float dh = fminf(r[3] / 5.0f, BBOX_CLIP);

            float pcx = dx * bw + cx;
            float pcy = dy * bh + cy;
            float pw  = expf(dw) * bw;
            float ph  = expf(dh) * bh;

            float bx1 = pcx - 0.5f * pw;
            float by1 = pcy - 0.5f * ph;
            float bx2 = pcx + 0.5f * pw - 1.0f;
            float by2 = pcy + 0.5f * ph - 1.0f;

            bx1 = fminf(fmaxf(bx1, 0.0f), IMG_W_M1);
            by1 = fminf(fmaxf(by1, 0.0f), IMG_H_M1);
            bx2 = fminf(fmaxf(bx2, 0.0f), IMG_W_M1);
            by2 = fminf(fmaxf(by2, 0.0f), IMG_H_M1);

            float* d = g_decT + (size_t)(c * NPROP + n) * 4;
            d[0] = bx1; d[1] = by1; d[2] = bx2; d[3] = by2;
        }
    }
    if (n == 0) {
        if (t == 0) g_count = 0;
        if (t < KTOP) { g_sel[t] = -1; g_selscore[t] = 0.0f; }
    }
}

// ---------------- Kernel B: compact + rank-sort + mask NMS + compact --------
#define KB_THREADS 256
#define KB_SMEM_WORDS (9 * 1024 + 1024 * 32 + 32 + 1)
#define KB_SMEM_BYTES (KB_SMEM_WORDS * 4)

__global__ void kB() {
    extern __shared__ unsigned int sm[];
    float*    u_sc   = (float*)sm;
    int*      u_idx  = (int*)(sm + 1024);
    float*    skey   = (float*)(sm + 2048);
    int*      sorig  = (int*)(sm + 3072);
    float*    sx1    = (float*)(sm + 4096);
    float*    sy1    = (float*)(sm + 5120);
    float*    sx2    = (float*)(sm + 6144);
    float*    sy2    = (float*)(sm + 7168);
    float*    sarea  = (float*)(sm + 8192);
    unsigned* mask   = sm + 9216;
    unsigned* s_rem  = sm + 9216 + 32768;
    int*      s_cnt  = (int*)(s_rem + 32);

    int c = blockIdx.x;
    int t = threadIdx.x;

    if (t == 0) *s_cnt = 0;
    __syncthreads();

    for (int e = t; e < NPROP; e += KB_THREADS) {
        float s = g_scoresT[c * NPROP + e];
        if (s > SCORE_TH) {
            int p = atomicAdd(s_cnt, 1);
            u_sc[p]  = s;
            u_idx[p] = e;
        }
    }
    __syncthreads();
    int nv = *s_cnt;
    if (nv == 0) return;
    int nwords = (nv + 31) >> 5;

    // rank-sort (score desc, orig idx asc)
    for (int ii = t; ii < nv; ii += KB_THREADS) {
        float ms = u_sc[ii];
        int   mi = u_idx[ii];
        int   r  = 0;
        for (int j = 0; j < nv; j++) {
            float sj = u_sc[j];
            int   ij = u_idx[j];
            r += (sj > ms) || (sj == ms && ij < mi);
        }
        skey[r]  = ms;
        sorig[r] = mi;
        const float* d = g_decT + (size_t)(c * NPROP + mi) * 4;
        float a0 = d[0], a1 = d[1], a2 = d[2], a3 = d[3];
        sx1[r] = a0; sy1[r] = a1; sx2[r] = a2; sy2[r] = a3;
        sarea[r] = (a2 - a0 + 1.0f) * (a3 - a1 + 1.0f);
    }
    __syncthreads();

    // IoU suppression bitmask
    int cells = nv * nwords;
    for (int cell = t; cell < cells; cell += KB_THREADS) {
        int i = cell / nwords;
        int w = cell - i * nwords;
        float x1 = sx1[i], y1 = sy1[i], x2 = sx2[i], y2 = sy2[i], ai = sarea[i];
        unsigned mword = 0;
        int jbase = w << 5;
        #pragma unroll 4
        for (int b = 0; b < 32; b++) {
            int j = jbase + b;
            if (j > i && j < nv) {
                float xx1 = fmaxf(x1, sx1[j]);
                float yy1 = fmaxf(y1, sy1[j]);
                float xx2 = fminf(x2, sx2[j]);
                float yy2 = fminf(y2, sy2[j]);
                float iw = fmaxf(xx2 - xx1 + 1.0f, 0.0f);
                float ih = fmaxf(yy2 - yy1 + 1.0f, 0.0f);
                float inter = iw * ih;
                float iou = inter / (ai + sarea[j] - inter);
                if (iou > NMS_TH) mword |= (1u << b);
            }
        }
        mask[(i << 5) + w] = mword;
    }
    if (t < 32 && t >= nwords) s_rem[t] = 0;
    __syncthreads();

    // greedy pass (warp 0; lane w owns word w)
    if (t < 32) {
        unsigned rem = 0;
        for (int wi = 0; wi < nwords; wi++) {
            unsigned remw = __shfl_sync(0xffffffffu, rem, wi);
            int rembits = nv - (wi << 5);
            unsigned validm = (rembits >= 32) ? 0xffffffffu : ((1u << rembits) - 1u);
            unsigned alive = (~remw) & validm;
            while (alive) {
                int b = __ffs(alive) - 1;
                int i = (wi << 5) + b;
                unsigned row = (t < nwords) ? mask[(i << 5) + t] : 0u;
                rem |= row;
                alive &= ~(1u << b);
                alive &= ~__shfl_sync(0xffffffffu, row, wi);
            }
        }
        if (t < nwords) s_rem[t] = rem;
    }
    __syncthreads();

    // compact survivors (first KTOP per class)
    for (int i = t; i < nv; i += KB_THREADS) {
        unsigned rw = s_rem[i >> 5];
        if (!((rw >> (i & 31)) & 1)) {
            int kr = 0;
            for (int w = 0; w < (i >> 5); w++) kr += __popc(~s_rem[w]);
            kr += __popc((~rw) & ((1u << (i & 31)) - 1u));
            if (kr < KTOP) {
                int p = atomicAdd(&g_count, 1);
                g_cscore[p] = skey[i];
                float* gb = g_cbox + (size_t)p * 4;
                gb[0] = sx1[i]; gb[1] = sy1[i]; gb[2] = sx2[i]; gb[3] = sy2[i];
                g_corig[p]  = sorig[i];
                g_cflat[p]  = c * NPROP + i;
                g_clabel[p] = c + 1;
            }
        }
    }
}

// ---------------- Kernel C: histogram-select + exact rank top-K -------------
#define TS_THREADS 1024
#define NBINS 1024
#define SELCAP 2048

__device__ __forceinline__ unsigned long long tk_key(float s, int flat) {
    return (((unsigned long long)__float_as_uint(s)) << 32) |
           (unsigned long long)(0xFFFFFFFFu - (unsigned)flat);
}

__global__ void kTop() {
    __shared__ int hist[NBINS];
    __shared__ int suf[NBINS];
    __shared__ int s_cut, s_cnt;
    __shared__ unsigned long long keys[SELCAP];
    __shared__ int sidx[SELCAP];

    int t = threadIdx.x;
    int M = g_count;
    if (M > CAP) M = CAP;
    if (M == 0) return;                 // g_sel pre-initialized to -1
    int Kwant = (M < KTOP) ? M : KTOP;

    if (t < NBINS) hist[t] = 0;
    if (t == 0) s_cnt = 0;
    __syncthreads();

    for (int i = t; i < M; i += TS_THREADS) {
        float s = g_cscore[i];
        int b = (int)(s * (float)NBINS);
        b = max(0, min(b, NBINS - 1));
        atomicAdd(&hist[b], 1);
    }
    __syncthreads();

    // suffix sums: suf[b] = count with bin >= b
    if (t < NBINS) suf[t] = hist[t];
    __syncthreads();
    #pragma unroll
    for (int off = 1; off < NBINS; off <<= 1) {
        int v = 0;
        if (t < NBINS && t + off < NBINS) v = suf[t + off];
        __syncthreads();
        if (t < NBINS) suf[t] += v;
        __syncthreads();
    }

    if (t < NBINS) {
        bool ok  = suf[t] >= Kwant;
        bool nxt = (t + 1 < NBINS) && (suf[t + 1] >= Kwant);
        if (ok && !nxt) s_cut = t;
    }
    __syncthreads();
    int cut = s_cut;

    // compact candidates above cutoff bin (all top-K are in here)
    for (int i = t; i < M; i += TS_THREADS) {
        float s = g_cscore[i];
        int b = (int)(s * (float)NBINS);
        b = max(0, min(b, NBINS - 1));
        if (b >= cut) {
            int p = atomicAdd(&s_cnt, 1);
            if (p < SELCAP) {
                keys[p] = tk_key(s, g_cflat[i]);
                sidx[p] = i;
            }
        }
    }
    __syncthreads();
    int Msel = s_cnt;
    if (Msel > SELCAP) Msel = SELCAP;

    // exact rank among the selected set
    for (int ii = t; ii < Msel; ii += TS_THREADS) {
        unsigned long long mk = keys[ii];
        int r = 0;
        for (int j = 0; j < Msel; j++) r += (keys[j] > mk);
        if (r < KTOP) {
            int gi = sidx[ii];
            g_sel[r] = gi;
            g_selscore[r] = g_cscore[gi];
        }
    }
}

// ---------------- Kernel D: write outputs + feature gather ------------------
__global__ void kD(const float* __restrict__ feats, float* __restrict__ out) {
    int k = blockIdx.x;
    int t = threadIdx.x;
    int sel = g_sel[k];
    const int OB = 0;
    const int OS = KTOP * 4;
    const int OF = KTOP * 4 + KTOP;
    const int OL = KTOP * 4 + KTOP + KTOP * FD;

    if (sel >= 0) {
        if (t == 0) {
            const float* gb = g_cbox + (size_t)sel * 4;
            out[OB + k * 4 + 0] = gb[0];
            out[OB + k * 4 + 1] = gb[1];
            out[OB + k * 4 + 2] = gb[2];
            out[OB + k * 4 + 3] = gb[3];
            out[OS + k] = g_selscore[k];
            out[OL + k] = (float)g_clabel[sel];
        }
        int orig = g_corig[sel];
        const float4* src = (const float4*)(feats + (size_t)orig * FD);
        float4* dst = (float4*)(out + OF + (size_t)k * FD);
        dst[t] = src[t];
    } else {
        if (t == 0) {
            out[OB + k * 4 + 0] = 0.0f;
            out[OB + k * 4 + 1] = 0.0f;
            out[OB + k * 4 + 2] = 0.0f;
            out[OB + k * 4 + 3] = 0.0f;
            out[OS + k] = 0.0f;
            out[OL + k] = 0.0f;
        }
        float4 z = make_float4(0.0f, 0.0f, 0.0f, 0.0f);
        float4* dst = (float4*)(out + OF + (size_t)k * FD);
        dst[t] = z;
    }
}

// ---------------- launch -----------------------------------------------------
extern "C" void kernel_launch(void* const* d_in, const int* in_sizes, int n_in,
                              void* d_out, int out_size) {
    const float* logits = (const float*)d_in[0];
    const float* reg    = (const float*)d_in[1];
    const float* props  = (const float*)d_in[2];
    const float* feats  = (const float*)d_in[3];
    float* out = (float*)d_out;

    static bool attr_done = false;
    if (!attr_done) {
        cudaFuncSetAttribute(kB, cudaFuncAttributeMaxDynamicSharedMemorySize,
                             KB_SMEM_BYTES);
        attr_done = true;
    }

    kA<<<NPROP, 128>>>(logits, reg, props);
    kB<<<NCLS, KB_THREADS, KB_SMEM_BYTES>>>();
    kTop<<<1, TS_THREADS>>>();
    kD<<<KTOP, 256>>>(feats, out);
}

// round 5
// speedup vs baseline: 5.9072x; 1.2433x over previous
#include <cuda_runtime.h>
#include <float.h>

#define NPROP 1024
#define NC    81
#define NCLS  80
#define FD    1024
#define KTOP  100
#define CAP   (NCLS * KTOP)
#define NBLK  80
#define NT    256

#define SCORE_TH 0.05f
#define NMS_TH   0.5f
#define BBOX_CLIP 4.135166556742356f
#define IMG_W_M1 1215.0f
#define IMG_H_M1 799.0f

// output layout (floats): boxes[100*4] | scores[100] | feats[100*1024] | labels[100]
#define OFF_S 400
#define OFF_F 500
#define OFF_L 102900

// ---------------- device scratch ------------
__device__ float g_scoresT[NCLS * NPROP];
__device__ float g_decT[NCLS * NPROP * 4];
__device__ int   g_count;
__device__ float g_cscore[CAP];
__device__ float g_cbox[CAP * 4];
__device__ int   g_corig[CAP];
__device__ int   g_cflat[CAP];
__device__ int   g_clabel[CAP];
__device__ int   g_selorig[KTOP];

// ---------------- inter-block barrier (self-resetting, replay-safe) ---------
__device__ unsigned g_ctr = 0;
__device__ volatile unsigned g_rel;

__device__ __forceinline__ void gbar() {
    __threadfence();
    __syncthreads();
    if (threadIdx.x == 0) {
        unsigned e = g_rel;
        if (atomicAdd(&g_ctr, 1u) == NBLK - 1u) {
            g_ctr = 0u;
            __threadfence();
            atomicAdd((unsigned*)&g_rel, 1u);
        } else {
            while (g_rel == e) { }
        }
    }
    __syncthreads();
}

__device__ __forceinline__ unsigned long long tk_key(float s, int flat) {
    return (((unsigned long long)__float_as_uint(s)) << 32) |
           (unsigned long long)(0xFFFFFFFFu - (unsigned)flat);
}

// dyn smem sized for phase B: 9*1024 + 1024*32 + 32 + 1 words
#define SMEM_WORDS (9 * 1024 + 1024 * 32 + 32 + 1)
#define SMEM_BYTES (SMEM_WORDS * 4)

__global__ void __launch_bounds__(NT, 1) kMain(
        const float* __restrict__ logits,
        const float* __restrict__ reg,
        const float* __restrict__ props,
        const float* __restrict__ feats,
        float* __restrict__ out) {
    extern __shared__ unsigned sm[];
    int t = threadIdx.x;
    int b = blockIdx.x;
    int wid = t >> 5, l = t & 31;

    if (b == 0 && t == 0) g_count = 0;

    // ================= Phase A: softmax + sparse decode (warp/proposal) =====
    for (int n = b * 8 + wid; n < NPROP; n += NBLK * 8) {
        const float* lg = logits + n * NC;
        float v0 = lg[l];
        float v1 = lg[l + 32];
        float v2 = -FLT_MAX;
        if (l < 17) v2 = lg[l + 64];

        float m = fmaxf(fmaxf(v0, v1), v2);
        #pragma unroll
        for (int off = 16; off; off >>= 1)
            m = fmaxf(m, __shfl_xor_sync(0xffffffffu, m, off));

        float e0 = expf(v0 - m);
        float e1 = expf(v1 - m);
        float e2 = (l < 17) ? expf(v2 - m) : 0.0f;
        float s = e0 + e1 + e2;
        #pragma unroll
        for (int off = 16; off; off >>= 1)
            s += __shfl_xor_sync(0xffffffffu, s, off);
        float inv = 1.0f / s;

        float pr[3] = { e0 * inv, e1 * inv, e2 * inv };
        int   cc[3] = { l, l + 32, l + 64 };
        bool havebox = false;
        float bw, bh, cx, cy;
        #pragma unroll
        for (int q = 0; q < 3; q++) {
            int c = cc[q];
            if (c >= 1 && c < NC) {
                float prob = pr[q];
                g_scoresT[(c - 1) * NPROP + n] = prob;
                if (prob > SCORE_TH) {
                    if (!havebox) {
                        float x1 = props[n * 4 + 0];
                        float y1 = props[n * 4 + 1];
                        float x2 = props[n * 4 + 2];
                        float y2 = props[n * 4 + 3];
                        bw = x2 - x1 + 1.0f;
                        bh = y2 - y1 + 1.0f;
                        cx = x1 + 0.5f * bw;
                        cy = y1 + 0.5f * bh;
                        havebox = true;
                    }
                    const float* r = reg + n * NC * 4 + c * 4;
                    float dx = r[0] / 10.0f;
                    float dy = r[1] / 10.0f;
                    float dw = fminf(r[2] / 5.0f, BBOX_CLIP);
                    float dh = fminf(r[3] / 5.0f, BBOX_CLIP);

                    float pcx = dx * bw + cx;
                    float pcy = dy * bh + cy;
                    float pw  = expf(dw) * bw;
                    float ph  = expf(dh) * bh;

                    float bx1 = pcx - 0.5f * pw;
                    float by1 = pcy - 0.5f * ph;
                    float bx2 = pcx + 0.5f * pw - 1.0f;
                    float by2 = pcy + 0.5f * ph - 1.0f;

                    bx1 = fminf(fmaxf(bx1, 0.0f), IMG_W_M1);
                    by1 = fminf(fmaxf(by1, 0.0f), IMG_H_M1);
                    bx2 = fminf(fmaxf(bx2, 0.0f), IMG_W_M1);
                    by2 = fminf(fmaxf(by2, 0.0f), IMG_H_M1);

                    float* d = g_decT + (size_t)((c - 1) * NPROP + n) * 4;
                    d[0] = bx1; d[1] = by1; d[2] = bx2; d[3] = by2;
                }
            }
        }
    }

    gbar();

    // ================= Phase B: per-class NMS (class = blockIdx) ============
    {
        float*    u_sc   = (float*)sm;
        int*      u_idx  = (int*)(sm + 1024);
        float*    skey   = (float*)(sm + 2048);
        int*      sorig  = (int*)(sm + 3072);
        float*    sx1    = (float*)(sm + 4096);
        float*    sy1    = (float*)(sm + 5120);
        float*    sx2    = (float*)(sm + 6144);
        float*    sy2    = (float*)(sm + 7168);
        float*    sarea  = (float*)(sm + 8192);
        unsigned* mask   = sm + 9216;
        unsigned* s_rem  = sm + 9216 + 32768;
        int*      s_cnt  = (int*)(s_rem + 32);

        int c = b;
        if (t == 0) *s_cnt = 0;
        __syncthreads();

        for (int e = t; e < NPROP; e += NT) {
            float s = g_scoresT[c * NPROP + e];
            if (s > SCORE_TH) {
                int p = atomicAdd(s_cnt, 1);
                u_sc[p]  = s;
                u_idx[p] = e;
            }
        }
        __syncthreads();
        int nv = *s_cnt;

        if (nv > 0) {
            int nwords = (nv + 31) >> 5;

            for (int ii = t; ii < nv; ii += NT) {
                float ms = u_sc[ii];
                int   mi = u_idx[ii];
                int   r  = 0;
                for (int j = 0; j < nv; j++) {
                    float sj = u_sc[j];
                    int   ij = u_idx[j];
                    r += (sj > ms) || (sj == ms && ij < mi);
                }
                skey[r]  = ms;
                sorig[r] = mi;
                const float* d = g_decT + (size_t)(c * NPROP + mi) * 4;
                float a0 = d[0], a1 = d[1], a2 = d[2], a3 = d[3];
                sx1[r] = a0; sy1[r] = a1; sx2[r] = a2; sy2[r] = a3;
                sarea[r] = (a2 - a0 + 1.0f) * (a3 - a1 + 1.0f);
            }
            __syncthreads();

            int cells = nv * nwords;
            for (int cell = t; cell < cells; cell += NT) {
                int i = cell / nwords;
                int w = cell - i * nwords;
                float x1 = sx1[i], y1 = sy1[i], x2 = sx2[i], y2 = sy2[i], ai = sarea[i];
                unsigned mword = 0;
                int jbase = w << 5;
                #pragma unroll 4
                for (int bb = 0; bb < 32; bb++) {
                    int j = jbase + bb;
                    if (j > i && j < nv) {
                        float xx1 = fmaxf(x1, sx1[j]);
                        float yy1 = fmaxf(y1, sy1[j]);
                        float xx2 = fminf(x2, sx2[j]);
                        float yy2 = fminf(y2, sy2[j]);
                        float iw = fmaxf(xx2 - xx1 + 1.0f, 0.0f);
                        float ih = fmaxf(yy2 - yy1 + 1.0f, 0.0f);
                        float inter = iw * ih;
                        float iou = inter / (ai + sarea[j] - inter);
                        if (iou > NMS_TH) mword |= (1u << bb);
                    }
                }
                mask[(i << 5) + w] = mword;
            }
            if (t < 32 && t >= nwords) s_rem[t] = 0;
            __syncthreads();

            if (t < 32) {
                unsigned rem = 0;
                for (int wi = 0; wi < nwords; wi++) {
                    unsigned remw = __shfl_sync(0xffffffffu, rem, wi);
                    int rembits = nv - (wi << 5);
                    unsigned validm = (rembits >= 32) ? 0xffffffffu : ((1u << rembits) - 1u);
                    unsigned alive = (~remw) & validm;
                    while (alive) {
                        int bb = __ffs(alive) - 1;
                        int i = (wi << 5) + bb;
                        unsigned row = (t < nwords) ? mask[(i << 5) + t] : 0u;
                        rem |= row;
                        alive &= ~(1u << bb);
                        alive &= ~__shfl_sync(0xffffffffu, row, wi);
                    }
                }
                if (t < nwords) s_rem[t] = rem;
            }
            __syncthreads();

            for (int i = t; i < nv; i += NT) {
                unsigned rw = s_rem[i >> 5];
                if (!((rw >> (i & 31)) & 1)) {
                    int kr = 0;
                    for (int w = 0; w < (i >> 5); w++) kr += __popc(~s_rem[w]);
                    kr += __popc((~rw) & ((1u << (i & 31)) - 1u));
                    if (kr < KTOP) {
                        int p = atomicAdd(&g_count, 1);
                        g_cscore[p] = skey[i];
                        float* gb = g_cbox + (size_t)p * 4;
                        gb[0] = sx1[i]; gb[1] = sy1[i]; gb[2] = sx2[i]; gb[3] = sy2[i];
                        g_corig[p]  = sorig[i];
                        g_cflat[p]  = c * NPROP + i;
                        g_clabel[p] = c + 1;
                    }
                }
            }
        }
    }

    gbar();

    // ================= Phase C: top-K + meta outputs (block 0 only) =========
    if (b == 0) {
        int* hist = (int*)sm;
        int* suf  = (int*)(sm + 256);
        unsigned long long* keys = (unsigned long long*)(sm + 512); // byte 2048, 8B aligned
        int* sidx = (int*)(sm + 512 + 4096);
        __shared__ int sc_cut, sc_cnt;

        // init all output meta slots + selorig
        for (int k = t; k < KTOP; k += NT) {
            out[k * 4 + 0] = 0.0f;
            out[k * 4 + 1] = 0.0f;
            out[k * 4 + 2] = 0.0f;
            out[k * 4 + 3] = 0.0f;
            out[OFF_S + k] = 0.0f;
            out[OFF_L + k] = 0.0f;
            g_selorig[k] = -1;
        }

        int M = g_count;
        if (M > CAP) M = CAP;
        if (M > 0) {
            hist[t] = 0;
            if (t == 0) sc_cnt = 0;
            __syncthreads();

            for (int i = t; i < M; i += NT) {
                int bb = (int)(g_cscore[i] * 256.0f);
                bb = max(0, min(bb, 255));
                atomicAdd(&hist[bb], 1);
            }
            __syncthreads();

            suf[t] = hist[t];
            __syncthreads();
            #pragma unroll
            for (int off = 1; off < 256; off <<= 1) {
                int v = (t + off < 256) ? suf[t + off] : 0;
                __syncthreads();
                suf[t] += v;
                __syncthreads();
            }

            int Kwant = (M < KTOP) ? M : KTOP;
            if (suf[t] >= Kwant && (t == 255 || suf[t + 1] < Kwant)) sc_cut = t;
            __syncthreads();
            int cut = sc_cut;

            for (int i = t; i < M; i += NT) {
                float sc = g_cscore[i];
                int bb = (int)(sc * 256.0f);
                bb = max(0, min(bb, 255));
                if (bb >= cut) {
                    int p = atomicAdd(&sc_cnt, 1);
                    if (p < 2048) {
                        keys[p] = tk_key(sc, g_cflat[i]);
                        sidx[p] = i;
                    }
                }
            }
            __syncthreads();
            int Msel = sc_cnt;
            if (Msel > 2048) Msel = 2048;

            for (int ii = t; ii < Msel; ii += NT) {
                unsigned long long mk = keys[ii];
                int r = 0;
                for (int j = 0; j < Msel; j++) r += (keys[j] > mk);
                if (r < KTOP) {
                    int gi = sidx[ii];
                    out[r * 4 + 0] = g_cbox[gi * 4 + 0];
                    out[r * 4 + 1] = g_cbox[gi * 4 + 1];
                    out[r * 4 + 2] = g_cbox[gi * 4 + 2];
                    out[r * 4 + 3] = g_cbox[gi * 4 + 3];
                    out[OFF_S + r] = g_cscore[gi];
                    out[OFF_L + r] = (float)g_clabel[gi];
                    g_selorig[r] = g_corig[gi];
                }
            }
        }
    }

    gbar();

    // ================= Phase D: feature gather ==============================
    for (int k = b; k < KTOP; k += NBLK) {
        int orig = g_selorig[k];
        float4* dst = (float4*)(out + OFF_F + (size_t)k * FD);
        if (orig >= 0) {
            const float4* src = (const float4*)(feats + (size_t)orig * FD);
            dst[t] = src[t];
        } else {
            dst[t] = make_float4(0.0f, 0.0f, 0.0f, 0.0f);
        }
    }
}

// ---------------- launch -----------------------------------------------------
extern "C" void kernel_launch(void* const* d_in, const int* in_sizes, int n_in,
                              void* d_out, int out_size) {
    const float* logits = (const float*)d_in[0];
    const float* reg    = (const float*)d_in[1];
    const float* props  = (const float*)d_in[2];
    const float* feats  = (const float*)d_in[3];
    float* out = (float*)d_out;

    static bool attr_done = false;
    if (!attr_done) {
        cudaFuncSetAttribute(kMain, cudaFuncAttributeMaxDynamicSharedMemorySize,
                             SMEM_BYTES);
        attr_done = true;
    }

    kMain<<<NBLK, NT, SMEM_BYTES>>>(logits, reg, props, feats, out);
}

// round 6
// speedup vs baseline: 7.2387x; 1.2254x over previous
#include <cuda_runtime.h>
#include <float.h>

#define NPROP 1024
#define NC    81
#define NCLS  80
#define FD    1024
#define KTOP  100
#define CAP   (NCLS * KTOP)
#define NBLK  80
#define NT    256
#define SELCAP 4096

#define SCORE_TH 0.05f
#define NMS_TH   0.5f
#define BBOX_CLIP 4.135166556742356f
#define IMG_W_M1 1215.0f
#define IMG_H_M1 799.0f

// output layout (floats): boxes[100*4] | scores[100] | feats[100*1024] | labels[100]
#define OFF_S 400
#define OFF_F 500
#define OFF_L 102900

// ---------------- device scratch ------------
__device__ int    g_ccnt[NCLS];                  // static zero; re-zeroed at end of each run
__device__ float  g_csc[NCLS * NPROP];           // per-class candidate scores
__device__ int    g_cid[NCLS * NPROP];           // per-class candidate proposal ids
__device__ float  g_decT[NCLS * NPROP * 4];      // decoded boxes by (class, proposal)
__device__ int    g_hist[256];
__device__ int    g_count;
__device__ unsigned long long g_ckey[CAP];
__device__ float4 g_cbox4[CAP];
__device__ int    g_corig[CAP];

// ---------------- inter-block barrier (self-resetting, replay-safe) ---------
__device__ unsigned g_ctr = 0;
__device__ volatile unsigned g_rel;

__device__ __forceinline__ void gbar() {
    __threadfence();
    __syncthreads();
    if (threadIdx.x == 0) {
        unsigned e = g_rel;
        if (atomicAdd(&g_ctr, 1u) == NBLK - 1u) {
            g_ctr = 0u;
            __threadfence();
            atomicAdd((unsigned*)&g_rel, 1u);
        } else {
            while (g_rel == e) { }
        }
    }
    __syncthreads();
}

__device__ __forceinline__ unsigned long long tk_key(float s, int flat) {
    return (((unsigned long long)__float_as_uint(s)) << 32) |
           (unsigned long long)(0xFFFFFFFFu - (unsigned)flat);
}

// dyn smem: 9*1024 + 32768 + 32 + 32 words
#define SMEM_WORDS (9 * 1024 + 32768 + 64)
#define SMEM_BYTES (SMEM_WORDS * 4)

__global__ void __launch_bounds__(NT, 1) kMain(
        const float* __restrict__ logits,
        const float* __restrict__ reg,
        const float* __restrict__ props,
        const float* __restrict__ feats,
        float* __restrict__ out) {
    extern __shared__ unsigned sm[];
    int t = threadIdx.x;
    int b = blockIdx.x;
    int wid = t >> 5, l = t & 31;

    if (b == 0 && t == 0) g_count = 0;
    if (b == 1 && t < 256) g_hist[t] = 0;

    // ================= Phase A: softmax + sparse decode + candidate push ====
    for (int n = b * 8 + wid; n < NPROP; n += NBLK * 8) {
        const float* lg = logits + n * NC;
        float v0 = lg[l];
        float v1 = lg[l + 32];
        float v2 = (l < 17) ? lg[l + 64] : -FLT_MAX;

        float m = fmaxf(fmaxf(v0, v1), v2);
        #pragma unroll
        for (int off = 16; off; off >>= 1)
            m = fmaxf(m, __shfl_xor_sync(0xffffffffu, m, off));

        float e0 = expf(v0 - m);
        float e1 = expf(v1 - m);
        float e2 = (l < 17) ? expf(v2 - m) : 0.0f;
        float s = e0 + e1 + e2;
        #pragma unroll
        for (int off = 16; off; off >>= 1)
            s += __shfl_xor_sync(0xffffffffu, s, off);
        float inv = 1.0f / s;

        float pr[3] = { e0 * inv, e1 * inv, e2 * inv };
        int   cc[3] = { l, l + 32, l + 64 };
        bool havebox = false;
        float bw, bh, cx, cy;
        #pragma unroll
        for (int q = 0; q < 3; q++) {
            int c = cc[q];
            if (c >= 1 && c < NC) {
                float prob = pr[q];
                if (prob > SCORE_TH) {
                    if (!havebox) {
                        float x1 = props[n * 4 + 0];
                        float y1 = props[n * 4 + 1];
                        float x2 = props[n * 4 + 2];
                        float y2 = props[n * 4 + 3];
                        bw = x2 - x1 + 1.0f;
                        bh = y2 - y1 + 1.0f;
                        cx = x1 + 0.5f * bw;
                        cy = y1 + 0.5f * bh;
                        havebox = true;
                    }
                    const float* r = reg + n * NC * 4 + c * 4;
                    float dx = r[0] / 10.0f;
                    float dy = r[1] / 10.0f;
                    float dw = fminf(r[2] / 5.0f, BBOX_CLIP);
                    float dh = fminf(r[3] / 5.0f, BBOX_CLIP);

                    float pcx = dx * bw + cx;
                    float pcy = dy * bh + cy;
                    float pw  = expf(dw) * bw;
                    float ph  = expf(dh) * bh;

                    float bx1 = fminf(fmaxf(pcx - 0.5f * pw, 0.0f), IMG_W_M1);
                    float by1 = fminf(fmaxf(pcy - 0.5f * ph, 0.0f), IMG_H_M1);
                    float bx2 = fminf(fmaxf(pcx + 0.5f * pw - 1.0f, 0.0f), IMG_W_M1);
                    float by2 = fminf(fmaxf(pcy + 0.5f * ph - 1.0f, 0.0f), IMG_H_M1);

                    float* d = g_decT + (size_t)((c - 1) * NPROP + n) * 4;
                    d[0] = bx1; d[1] = by1; d[2] = bx2; d[3] = by2;

                    int slot = atomicAdd(&g_ccnt[c - 1], 1);
                    g_csc[(c - 1) * NPROP + slot] = prob;
                    g_cid[(c - 1) * NPROP + slot] = n;
                }
            }
        }
    }

    gbar();

    // ================= Phase B: per-class NMS (class = blockIdx) ============
    {
        float*    u_sc   = (float*)sm;
        int*      u_idx  = (int*)(sm + 1024);
        float*    skey   = (float*)(sm + 2048);
        int*      sorig  = (int*)(sm + 3072);
        float*    sx1    = (float*)(sm + 4096);
        float*    sy1    = (float*)(sm + 5120);
        float*    sx2    = (float*)(sm + 6144);
        float*    sy2    = (float*)(sm + 7168);
        float*    sarea  = (float*)(sm + 8192);
        unsigned* mask   = sm + 9216;
        unsigned* s_rem  = sm + 9216 + 32768;
        unsigned* s_sup  = s_rem + 32;
        __shared__ int s_base;

        int c = b;
        int nv = g_ccnt[c];

        for (int i = t; i < nv; i += NT) {
            u_sc[i]  = g_csc[c * NPROP + i];
            u_idx[i] = g_cid[c * NPROP + i];
        }
        __syncthreads();

        if (nv > 0) {
            int nwords = (nv + 31) >> 5;

            // rank-sort (score desc, orig idx asc)
            for (int ii = t; ii < nv; ii += NT) {
                float ms = u_sc[ii];
                int   mi = u_idx[ii];
                int   r  = 0;
                for (int j = 0; j < nv; j++) {
                    float sj = u_sc[j];
                    int   ij = u_idx[j];
                    r += (sj > ms) || (sj == ms && ij < mi);
                }
                skey[r]  = ms;
                sorig[r] = mi;
                const float* d = g_decT + (size_t)(c * NPROP + mi) * 4;
                float a0 = d[0], a1 = d[1], a2 = d[2], a3 = d[3];
                sx1[r] = a0; sy1[r] = a1; sx2[r] = a2; sy2[r] = a3;
                sarea[r] = (a2 - a0 + 1.0f) * (a3 - a1 + 1.0f);
            }
            __syncthreads();

            // IoU suppression bitmask (bit j of mask[i][w]: i suppresses j, j>i)
            int cells = nv * nwords;
            for (int cell = t; cell < cells; cell += NT) {
                int i = cell / nwords;
                int w = cell - i * nwords;
                float x1 = sx1[i], y1 = sy1[i], x2 = sx2[i], y2 = sy2[i], ai = sarea[i];
                unsigned mword = 0;
                int jbase = w << 5;
                #pragma unroll 4
                for (int bb = 0; bb < 32; bb++) {
                    int j = jbase + bb;
                    if (j > i && j < nv) {
                        float xx1 = fmaxf(x1, sx1[j]);
                        float yy1 = fmaxf(y1, sy1[j]);
                        float xx2 = fminf(x2, sx2[j]);
                        float yy2 = fminf(y2, sy2[j]);
                        float iw = fmaxf(xx2 - xx1 + 1.0f, 0.0f);
                        float ih = fmaxf(yy2 - yy1 + 1.0f, 0.0f);
                        float inter = iw * ih;
                        float iou = inter / (ai + sarea[j] - inter);
                        if (iou > NMS_TH) mword |= (1u << bb);
                    }
                }
                mask[(i << 5) + w] = mword;
            }
            __syncthreads();

            // sup[w] = OR over all rows (bit j set => j has some potential suppressor)
            if (t < 32) {
                unsigned o = 0;
                if (t < nwords)
                    for (int i = 0; i < nv; i++) o |= mask[(i << 5) + t];
                s_sup[t] = o;
            }
            __syncthreads();

            // warp 0: rem = OR rows of certain-kept; then short serial walk on uncertain
            if (t < 32) {
                unsigned rem = 0;
                if (t < nwords) {
                    for (int i = 0; i < nv; i++) {
                        bool certain = !((s_sup[i >> 5] >> (i & 31)) & 1u);
                        if (certain) rem |= mask[(i << 5) + t];
                    }
                }
                for (int wi = 0; wi < nwords; wi++) {
                    int rembits = nv - (wi << 5);
                    unsigned validm = (rembits >= 32) ? 0xffffffffu : ((1u << rembits) - 1u);
                    unsigned remw = __shfl_sync(0xffffffffu, rem, wi);
                    unsigned alive = s_sup[wi] & validm & ~remw;
                    while (alive) {
                        int bb = __ffs(alive) - 1;
                        int j = (wi << 5) + bb;
                        unsigned row = (t < nwords) ? mask[(j << 5) + t] : 0u;
                        rem |= row;
                        alive &= ~(1u << bb);
                        alive &= ~__shfl_sync(0xffffffffu, row, wi);
                    }
                }
                s_rem[t] = (t < nwords) ? rem : 0u;
            }
            __syncthreads();

            // single base atomic per class
            if (t == 0) {
                int tot = 0;
                for (int w = 0; w < nwords; w++) {
                    int rembits = nv - (w << 5);
                    unsigned validm = (rembits >= 32) ? 0xffffffffu : ((1u << rembits) - 1u);
                    tot += __popc((~s_rem[w]) & validm);
                }
                if (tot > KTOP) tot = KTOP;
                s_base = atomicAdd(&g_count, tot);
            }
            __syncthreads();
            int base = s_base;

            // compact survivors (first KTOP per class), coalesced-ish writes
            for (int i = t; i < nv; i += NT) {
                unsigned rw = s_rem[i >> 5];
                if (!((rw >> (i & 31)) & 1)) {
                    int kr = 0;
                    for (int w = 0; w < (i >> 5); w++) kr += __popc(~s_rem[w]);
                    kr += __popc((~rw) & ((1u << (i & 31)) - 1u));
                    if (kr < KTOP) {
                        int p = base + kr;
                        float sc = skey[i];
                        g_ckey[p]  = tk_key(sc, c * NPROP + i);
                        g_cbox4[p] = make_float4(sx1[i], sy1[i], sx2[i], sy2[i]);
                        g_corig[p] = sorig[i];
                        int bb = (int)(sc * 256.0f);
                        bb = max(0, min(bb, 255));
                        atomicAdd(&g_hist[bb], 1);
                    }
                }
            }
        }
    }

    gbar();

    // ================= Phase C: distributed top-K + outputs + gather ========
    {
        int* suf = (int*)sm;
        unsigned long long* skeys = (unsigned long long*)(sm + 512); // byte 2048
        int* sgid = (int*)(sm + 512 + 2 * SELCAP);
        __shared__ int sc_cnt, sc_cut;
        __shared__ int s_nw;
        __shared__ int w_r[128], w_gi[128];

        int M = g_count;
        if (M > CAP) M = CAP;
        int Kfound = (M < KTOP) ? M : KTOP;

        if (t == 0) { sc_cnt = 0; s_nw = 0; }
        suf[t] = g_hist[t];
        __syncthreads();
        #pragma unroll
        for (int off = 1; off < 256; off <<= 1) {
            int v = (t + off < 256) ? suf[t + off] : 0;
            __syncthreads();
            suf[t] += v;
            __syncthreads();
        }

        if (M > 0) {
            if (suf[t] >= Kfound && (t == 255 || suf[t + 1] < Kfound)) sc_cut = t;
            __syncthreads();
            int cut = sc_cut;

            // compact candidates above cut (same set in every block)
            for (int i = t; i < M; i += NT) {
                unsigned long long key = g_ckey[i];
                float sc = __uint_as_float((unsigned)(key >> 32));
                int bb = (int)(sc * 256.0f);
                bb = max(0, min(bb, 255));
                if (bb >= cut) {
                    int p = atomicAdd(&sc_cnt, 1);
                    if (p < SELCAP) { skeys[p] = key; sgid[p] = i; }
                }
            }
            __syncthreads();
            int Msel = sc_cnt;
            if (Msel > SELCAP) Msel = SELCAP;

            // rank candidates owned by this block
            for (int ii = t; ii < Msel; ii += NT) {
                int gi = sgid[ii];
                if (gi % NBLK != b) continue;
                unsigned long long mk = skeys[ii];
                int r = 0;
                for (int j = 0; j < Msel; j++) r += (skeys[j] > mk);
                if (r < KTOP) {
                    int p = atomicAdd(&s_nw, 1);
                    w_r[p]  = r;
                    w_gi[p] = gi;
                }
            }
            __syncthreads();

            // write winners (meta + feature gather, block-cooperative)
            int nw = s_nw;
            for (int e = 0; e < nw; e++) {
                int r  = w_r[e];
                int gi = w_gi[e];
                if (t == 0) {
                    unsigned long long key = g_ckey[gi];
                    float sc = __uint_as_float((unsigned)(key >> 32));
                    unsigned flat = 0xFFFFFFFFu - (unsigned)(key & 0xFFFFFFFFu);
                    float4 bx = g_cbox4[gi];
                    ((float4*)out)[r] = bx;
                    out[OFF_S + r] = sc;
                    out[OFF_L + r] = (float)(flat / NPROP + 1);
                }
                int orig = g_corig[gi];
                const float4* src = (const float4*)(feats + (size_t)orig * FD);
                float4* dst = (float4*)(out + OFF_F + (size_t)r * FD);
                dst[t] = src[t];
            }
        }

        // zero-fill unfilled slots [Kfound, KTOP)
        for (int k = Kfound + b; k < KTOP; k += NBLK) {
            if (t == 0) {
                ((float4*)out)[k] = make_float4(0.0f, 0.0f, 0.0f, 0.0f);
                out[OFF_S + k] = 0.0f;
                out[OFF_L + k] = 0.0f;
            }
            float4* dst = (float4*)(out + OFF_F + (size_t)k * FD);
            dst[t] = make_float4(0.0f, 0.0f, 0.0f, 0.0f);
        }

        // reset per-class counters for next replay (all reads happened in phase B)
        if (b == 0 && t < NCLS) g_ccnt[t] = 0;
    }
}

// ---------------- launch -----------------------------------------------------
extern "C" void kernel_launch(void* const* d_in, const int* in_sizes, int n_in,
                              void* d_out, int out_size) {
    const float* logits = (const float*)d_in[0];
    const float* reg    = (const float*)d_in[1];
    const float* props  = (const float*)d_in[2];
    const float* feats  = (const float*)d_in[3];
    float* out = (float*)d_out;

    static bool attr_done = false;
    if (!attr_done) {
        cudaFuncSetAttribute(kMain, cudaFuncAttributeMaxDynamicSharedMemorySize,
                             SMEM_BYTES);
        attr_done = true;
    }

    kMain<<<NBLK, NT, SMEM_BYTES>>>(logits, reg, props, feats, out);
}